// round 9
// baseline (speedup 1.0000x reference)
#include <cuda_runtime.h>
#include <cuda_bf16.h>
#include <cstddef>

#define N_NODES 50000
#define N_EDGES 800000
#define D_IN    128
#define D_HID   256
#define D_OUT   128

// ---------------- device scratch (static, allocation-free) ----------------
// Only ever referenced from DEVICE code (never from host).
__device__ int   g_is64;                       // 1 if edge_index is int64, 0 if int32
__device__ int   g_cnt[N_NODES];
__device__ int   g_rowstart[N_NODES + 1];
__device__ int   g_work[N_NODES];
__device__ int   g_csr_src[N_EDGES];
__device__ float g_z[(size_t)N_NODES * D_IN];  // layer1 agg; reused as z = h@W2_l
__device__ float g_h[(size_t)N_NODES * D_HID];

// ---------------- edge_index dtype detection ----------------
// int64 little-endian values < 2^31 have every odd 32-bit word == 0.
// For int32 node ids, an odd word is 0 only if that id happens to be 0
// (prob ~(1/50000)^32 over 32 words) -> robust discriminator.
__global__ void detect_k(const int* __restrict__ ei32) {
    if (threadIdx.x == 0 && blockIdx.x == 0) {
        int is64 = 1;
        #pragma unroll
        for (int i = 1; i < 64; i += 2)
            if (ei32[i] != 0) is64 = 0;
        g_is64 = is64;
    }
}

__device__ __forceinline__ int load_edge(const void* ei, size_t idx, int is64) {
    if (is64) return (int)((const long long*)ei)[idx];
    return ((const int*)ei)[idx];
}

// ---------------- CSR build ----------------
__global__ void zero_cnt_k() {
    int i = blockIdx.x * blockDim.x + threadIdx.x;
    if (i < N_NODES) g_cnt[i] = 0;
}

__global__ void count_k(const void* __restrict__ ei) {
    int i = blockIdx.x * blockDim.x + threadIdx.x;
    if (i < N_EDGES) {
        int is64 = g_is64;
        int d = load_edge(ei, (size_t)N_EDGES + i, is64);   // dst row
        if ((unsigned)d < (unsigned)N_NODES) atomicAdd(&g_cnt[d], 1);
    }
}

// single-block exclusive scan over g_cnt -> g_rowstart and g_work
__global__ void scan_k() {
    __shared__ int sh[1024];
    __shared__ int carry;
    int t = threadIdx.x;
    if (t == 0) carry = 0;
    __syncthreads();
    for (int base = 0; base < N_NODES; base += 1024) {
        int i = base + t;
        int v = (i < N_NODES) ? g_cnt[i] : 0;
        sh[t] = v;
        __syncthreads();
        #pragma unroll
        for (int off = 1; off < 1024; off <<= 1) {
            int add = (t >= off) ? sh[t - off] : 0;
            __syncthreads();
            sh[t] += add;
            __syncthreads();
        }
        int incl = sh[t];
        if (i < N_NODES) {
            int excl = carry + incl - v;
            g_rowstart[i] = excl;
            g_work[i]     = excl;
        }
        __syncthreads();
        if (t == 1023) sh[0] = carry + incl;
        __syncthreads();
        if (t == 0) carry = sh[0];
        __syncthreads();
    }
    if (t == 0) g_rowstart[N_NODES] = carry;
}

__global__ void place_k(const void* __restrict__ ei) {
    int i = blockIdx.x * blockDim.x + threadIdx.x;
    if (i < N_EDGES) {
        int is64 = g_is64;
        int s = load_edge(ei, (size_t)i, is64);              // src row
        int d = load_edge(ei, (size_t)N_EDGES + i, is64);    // dst row
        if ((unsigned)d < (unsigned)N_NODES && (unsigned)s < (unsigned)N_NODES) {
            int pos = atomicAdd(&g_work[d], 1);
            g_csr_src[pos] = s;
        }
    }
}

// ---------------- gather-mean body: one warp per destination node (F=128) ----------------
template <int ADD>
__device__ __forceinline__ void gather128_body(const float* __restrict__ feat,
                                               float* __restrict__ agg) {
    int warp = (blockIdx.x * blockDim.x + threadIdx.x) >> 5;
    int lane = threadIdx.x & 31;
    if (warp >= N_NODES) return;
    int beg = g_rowstart[warp], end = g_rowstart[warp + 1];
    float4 acc = make_float4(0.f, 0.f, 0.f, 0.f);
    for (int e = beg; e < end; e++) {
        int s = g_csr_src[e];
        float4 v = ((const float4*)(feat + (size_t)s * 128))[lane];
        acc.x += v.x; acc.y += v.y; acc.z += v.z; acc.w += v.w;
    }
    int deg = end - beg;
    float scale = 1.0f / (float)(deg > 0 ? deg : 1);
    float4* o = (float4*)(agg + (size_t)warp * 128);
    float4 r;
    if (ADD) {
        float4 prev = o[lane];
        r.x = prev.x + acc.x * scale; r.y = prev.y + acc.y * scale;
        r.z = prev.z + acc.z * scale; r.w = prev.w + acc.w * scale;
    } else {
        r.x = acc.x * scale; r.y = acc.y * scale;
        r.z = acc.z * scale; r.w = acc.w * scale;
    }
    o[lane] = r;
}

__global__ void gather_x_to_z_k(const float* __restrict__ x) {
    gather128_body<0>(x, g_z);
}
__global__ void gather_z_add_out_k(float* __restrict__ out) {
    gather128_body<1>(g_z, out);
}

// ---------------- fused dual GEMM body: Out = A@Wl + X@Wr + bias (+relu) ----------------
// A, X: [N, K] row-major;  Wl, Wr: [K, M] row-major;  Out: [N, M]
// 128x64 output tile per 256-thread block, BK=16, 8x4 microtile per thread (dual).
__device__ __forceinline__ void sage_gemm_body(
    const float* __restrict__ A, const float* __restrict__ X,
    const float* __restrict__ Wl, const float* __restrict__ Wr,
    const float* __restrict__ bias, float* __restrict__ Out,
    int N, int K, int M, int relu)
{
    __shared__ float sAa[16][128];
    __shared__ float sAx[16][128];
    __shared__ float sWl[16][64];
    __shared__ float sWr[16][64];

    const int tid = threadIdx.x;
    const int tx = tid & 15;
    const int ty = tid >> 4;
    const int tx4 = tx * 4, ty8 = ty * 8;
    const int row0 = blockIdx.y * 128;
    const int col0 = blockIdx.x * 64;

    const int ar = tid >> 1;           // 0..127 : tile row
    const int ak = (tid & 1) * 8;      // 0 or 8 : k offset
    const int wk = tid >> 4;           // 0..15 : W tile k
    const int wc = (tid & 15) * 4;     // 0..60 : W tile col

    const int arow = row0 + ar;
    const bool arow_ok = (arow < N);

    float acc[8][4];
    #pragma unroll
    for (int i = 0; i < 8; i++)
        #pragma unroll
        for (int j = 0; j < 4; j++) acc[i][j] = 0.f;

    for (int k0 = 0; k0 < K; k0 += 16) {
        float4 va0 = make_float4(0.f, 0.f, 0.f, 0.f), va1 = va0;
        float4 vx0 = va0, vx1 = va0;
        if (arow_ok) {
            const float* ap = A + (size_t)arow * K + k0 + ak;
            const float* xp = X + (size_t)arow * K + k0 + ak;
            va0 = *(const float4*)(ap);
            va1 = *(const float4*)(ap + 4);
            vx0 = *(const float4*)(xp);
            vx1 = *(const float4*)(xp + 4);
        }
        sAa[ak + 0][ar] = va0.x; sAa[ak + 1][ar] = va0.y;
        sAa[ak + 2][ar] = va0.z; sAa[ak + 3][ar] = va0.w;
        sAa[ak + 4][ar] = va1.x; sAa[ak + 5][ar] = va1.y;
        sAa[ak + 6][ar] = va1.z; sAa[ak + 7][ar] = va1.w;
        sAx[ak + 0][ar] = vx0.x; sAx[ak + 1][ar] = vx0.y;
        sAx[ak + 2][ar] = vx0.z; sAx[ak + 3][ar] = vx0.w;
        sAx[ak + 4][ar] = vx1.x; sAx[ak + 5][ar] = vx1.y;
        sAx[ak + 6][ar] = vx1.z; sAx[ak + 7][ar] = vx1.w;

        *(float4*)&sWl[wk][wc] = *(const float4*)(Wl + (size_t)(k0 + wk) * M + col0 + wc);
        *(float4*)&sWr[wk][wc] = *(const float4*)(Wr + (size_t)(k0 + wk) * M + col0 + wc);

        __syncthreads();

        #pragma unroll
        for (int k = 0; k < 16; k++) {
            float4 a0 = *(const float4*)&sAa[k][ty8];
            float4 a1 = *(const float4*)&sAa[k][ty8 + 4];
            float4 x0 = *(const float4*)&sAx[k][ty8];
            float4 x1 = *(const float4*)&sAx[k][ty8 + 4];
            float4 bl = *(const float4*)&sWl[k][tx4];
            float4 br = *(const float4*)&sWr[k][tx4];
            float a_[8] = {a0.x, a0.y, a0.z, a0.w, a1.x, a1.y, a1.z, a1.w};
            float x_[8] = {x0.x, x0.y, x0.z, x0.w, x1.x, x1.y, x1.z, x1.w};
            float l_[4] = {bl.x, bl.y, bl.z, bl.w};
            float r_[4] = {br.x, br.y, br.z, br.w};
            #pragma unroll
            for (int i = 0; i < 8; i++)
                #pragma unroll
                for (int j = 0; j < 4; j++)
                    acc[i][j] += a_[i] * l_[j] + x_[i] * r_[j];
        }
        __syncthreads();
    }

    #pragma unroll
    for (int i = 0; i < 8; i++) {
        int r = row0 + ty8 + i;
        if (r < N) {
            float4 o;
            o.x = acc[i][0] + bias[col0 + tx4 + 0];
            o.y = acc[i][1] + bias[col0 + tx4 + 1];
            o.z = acc[i][2] + bias[col0 + tx4 + 2];
            o.w = acc[i][3] + bias[col0 + tx4 + 3];
            if (relu) {
                o.x = fmaxf(o.x, 0.f); o.y = fmaxf(o.y, 0.f);
                o.z = fmaxf(o.z, 0.f); o.w = fmaxf(o.w, 0.f);
            }
            *(float4*)(Out + (size_t)r * M + col0 + tx4) = o;
        }
    }
}

// ---------------- single GEMM body: Out = A@W (+ optional bias) ----------------
__device__ __forceinline__ void gemm_single_body(
    const float* __restrict__ A, const float* __restrict__ W,
    const float* __restrict__ bias, float* __restrict__ Out,
    int N, int K, int M)
{
    __shared__ float sA[16][128];
    __shared__ float sW[16][64];

    const int tid = threadIdx.x;
    const int tx = tid & 15;
    const int ty = tid >> 4;
    const int tx4 = tx * 4, ty8 = ty * 8;
    const int row0 = blockIdx.y * 128;
    const int col0 = blockIdx.x * 64;

    const int ar = tid >> 1;
    const int ak = (tid & 1) * 8;
    const int wk = tid >> 4;
    const int wc = (tid & 15) * 4;

    const int arow = row0 + ar;
    const bool arow_ok = (arow < N);

    float acc[8][4];
    #pragma unroll
    for (int i = 0; i < 8; i++)
        #pragma unroll
        for (int j = 0; j < 4; j++) acc[i][j] = 0.f;

    for (int k0 = 0; k0 < K; k0 += 16) {
        float4 va0 = make_float4(0.f, 0.f, 0.f, 0.f), va1 = va0;
        if (arow_ok) {
            const float* ap = A + (size_t)arow * K + k0 + ak;
            va0 = *(const float4*)(ap);
            va1 = *(const float4*)(ap + 4);
        }
        sA[ak + 0][ar] = va0.x; sA[ak + 1][ar] = va0.y;
        sA[ak + 2][ar] = va0.z; sA[ak + 3][ar] = va0.w;
        sA[ak + 4][ar] = va1.x; sA[ak + 5][ar] = va1.y;
        sA[ak + 6][ar] = va1.z; sA[ak + 7][ar] = va1.w;

        *(float4*)&sW[wk][wc] = *(const float4*)(W + (size_t)(k0 + wk) * M + col0 + wc);

        __syncthreads();

        #pragma unroll
        for (int k = 0; k < 16; k++) {
            float4 a0 = *(const float4*)&sA[k][ty8];
            float4 a1 = *(const float4*)&sA[k][ty8 + 4];
            float4 wv = *(const float4*)&sW[k][tx4];
            float a_[8] = {a0.x, a0.y, a0.z, a0.w, a1.x, a1.y, a1.z, a1.w};
            float w_[4] = {wv.x, wv.y, wv.z, wv.w};
            #pragma unroll
            for (int i = 0; i < 8; i++)
                #pragma unroll
                for (int j = 0; j < 4; j++)
                    acc[i][j] += a_[i] * w_[j];
        }
        __syncthreads();
    }

    #pragma unroll
    for (int i = 0; i < 8; i++) {
        int r = row0 + ty8 + i;
        if (r < N) {
            float4 o;
            float bx = bias ? bias[col0 + tx4 + 0] : 0.f;
            float by = bias ? bias[col0 + tx4 + 1] : 0.f;
            float bz = bias ? bias[col0 + tx4 + 2] : 0.f;
            float bw = bias ? bias[col0 + tx4 + 3] : 0.f;
            o.x = acc[i][0] + bx; o.y = acc[i][1] + by;
            o.z = acc[i][2] + bz; o.w = acc[i][3] + bw;
            *(float4*)(Out + (size_t)r * M + col0 + tx4) = o;
        }
    }
}

// ---------------- GEMM wrappers binding scratch symbols (device side) ----------------
__global__ __launch_bounds__(256) void gemm_l1_k(
    const float* __restrict__ x, const float* __restrict__ W1l,
    const float* __restrict__ W1r, const float* __restrict__ b1)
{
    sage_gemm_body(g_z, x, W1l, W1r, b1, g_h, N_NODES, D_IN, D_HID, 1);
}

__global__ __launch_bounds__(256) void gemm_l2z_k(const float* __restrict__ W2l)
{
    gemm_single_body(g_h, W2l, nullptr, g_z, N_NODES, D_HID, D_OUT);
}

__global__ __launch_bounds__(256) void gemm_l2o_k(
    const float* __restrict__ W2r, const float* __restrict__ b2,
    float* __restrict__ out)
{
    gemm_single_body(g_h, W2r, b2, out, N_NODES, D_HID, D_OUT);
}

// ---------------- launch ----------------
extern "C" void kernel_launch(void* const* d_in, const int* in_sizes, int n_in,
                              void* d_out, int out_size) {
    const float* x   = (const float*)d_in[0];
    const void*  ei  = d_in[1];                 // int32 or int64; detected at runtime
    const float* W1l = (const float*)d_in[2];
    const float* b1  = (const float*)d_in[3];
    const float* W1r = (const float*)d_in[4];
    const float* W2l = (const float*)d_in[5];
    const float* b2  = (const float*)d_in[6];
    const float* W2r = (const float*)d_in[7];
    float*       out = (float*)d_out;

    // CSR build (per launch; deterministic)
    detect_k<<<1, 32>>>((const int*)ei);
    zero_cnt_k<<<(N_NODES + 255) / 256, 256>>>();
    count_k<<<(N_EDGES + 255) / 256, 256>>>(ei);
    scan_k<<<1, 1024>>>();
    place_k<<<(N_EDGES + 255) / 256, 256>>>(ei);

    const int gather_blocks = (N_NODES * 32 + 255) / 256;
    const dim3 g1(D_HID / 64, (N_NODES + 127) / 128);
    const dim3 g2(D_OUT / 64, (N_NODES + 127) / 128);

    // Layer 1: g_z = mean_agg(x) ; g_h = relu(g_z@W1_l + x@W1_r + b1)
    gather_x_to_z_k<<<gather_blocks, 256>>>(x);
    gemm_l1_k<<<g1, 256>>>(x, W1l, W1r, b1);

    // Layer 2 (mean-linearity reorder):
    //   g_z = g_h@W2_l ; out = g_h@W2_r + b2 ; out += mean_agg(g_z)
    gemm_l2z_k<<<g2, 256>>>(W2l);
    gemm_l2o_k<<<g2, 256>>>(W2r, b2, out);
    gather_z_add_out_k<<<gather_blocks, 256>>>(out);
}